// round 2
// baseline (speedup 1.0000x reference)
#include <cuda_runtime.h>
#include <cstdint>

// Problem constants (fixed by the reference):
//   x: (B=16384, F=128) f32, p: (B, C=8) f32,
//   W: (F, C*C=64, R=64) f32 -> flat (128, 4096),
//   b: (C, C, R) f32 -> flat (4096), out: (B, C, R) f32 -> (B, 512)
// logits[b, n] = sum_f x[b,f] * W[f*4096 + n],  n = c*512 + d*64 + r
// M = softmax over d;  out[b, d*64+r] = sum_c p[b,c] * M[b, c, d, r]

#define NTHREADS 256
#define BM 32          // batch rows per block
#define TM 8           // rows per thread (ty in 0..3)
#define KKC 16         // K-chunk depth
#define NCHUNK 8       // 128 / 16
#define NC 8           // C
#define NR 64          // R
#define BN 512         // C * R (one c-group of columns)
#define NF 128         // features
#define AS_STRIDE 36   // padded stride for transposed x tile (16B-aligned reads)

__device__ __forceinline__ uint32_t smem_u32(const void* p) {
    return (uint32_t)__cvta_generic_to_shared(p);
}

__device__ __forceinline__ void prefetch_chunk(const float* __restrict__ W,
                                               float* __restrict__ Bs,
                                               int c, int kk, int buf, int tid) {
    const float* src_base = W + (size_t)kk * KKC * 4096 + c * BN;
    float* dst_base = Bs + buf * (KKC * BN);
    // 16*512 floats = 2048 float4; 8 per thread
    #pragma unroll
    for (int j = 0; j < 8; j++) {
        int idx = tid + j * NTHREADS;   // float4 index
        int k   = idx >> 7;             // 128 float4 per 512-wide row
        int n4  = idx & 127;
        uint32_t dsh = smem_u32(dst_base + k * BN + n4 * 4);
        const float* src = src_base + (size_t)k * 4096 + n4 * 4;
        asm volatile("cp.async.cg.shared.global [%0], [%1], 16;\n"
                     :: "r"(dsh), "l"(src));
    }
    asm volatile("cp.async.commit_group;\n");
}

__global__ __launch_bounds__(NTHREADS, 1)
void crowds_fused_kernel(const float* __restrict__ x,
                         const float* __restrict__ p,
                         const float* __restrict__ W,
                         const float* __restrict__ bias,
                         float* __restrict__ out) {
    extern __shared__ float smem[];
    float* As    = smem;                       // [128][AS_STRIDE] transposed x tile
    float* Bs    = As + NF * AS_STRIDE;        // [2][16][512] W chunks
    float* biass = Bs + 2 * KKC * BN;          // [4096]
    float* ps    = biass + NC * BN;            // [32][8]

    const int tid = threadIdx.x;
    const int tx  = tid & 63;                  // r index (0..63)
    const int ty  = tid >> 6;                  // row group (0..3)
    const int rowbase = blockIdx.x * BM;

    // ---- stage x tile (transposed), bias, p ----
    for (int i = tid; i < BM * (NF / 4); i += NTHREADS) {
        int row = i >> 5;                      // 32 float4 per row
        int c4  = i & 31;
        float4 v = *reinterpret_cast<const float4*>(
            x + (size_t)(rowbase + row) * NF + c4 * 4);
        As[(c4 * 4 + 0) * AS_STRIDE + row] = v.x;
        As[(c4 * 4 + 1) * AS_STRIDE + row] = v.y;
        As[(c4 * 4 + 2) * AS_STRIDE + row] = v.z;
        As[(c4 * 4 + 3) * AS_STRIDE + row] = v.w;
    }
    for (int i = tid; i < NC * BN; i += NTHREADS) biass[i] = bias[i];
    if (tid < BM * NC) ps[tid] = p[(size_t)rowbase * NC + tid];
    __syncthreads();

    float outreg[TM][NC];
    #pragma unroll
    for (int m = 0; m < TM; m++)
        #pragma unroll
        for (int d = 0; d < NC; d++) outreg[m][d] = 0.f;

    for (int c = 0; c < NC; c++) {
        float acc[TM][NC];
        #pragma unroll
        for (int m = 0; m < TM; m++)
            #pragma unroll
            for (int d = 0; d < NC; d++) acc[m][d] = 0.f;

        prefetch_chunk(W, Bs, c, 0, 0, tid);

        for (int kk = 0; kk < NCHUNK; kk++) {
            if (kk + 1 < NCHUNK) {
                prefetch_chunk(W, Bs, c, kk + 1, (kk + 1) & 1, tid);
                asm volatile("cp.async.wait_group 1;\n");
            } else {
                asm volatile("cp.async.wait_group 0;\n");
            }
            __syncthreads();

            const float* B0 = Bs + (kk & 1) * (KKC * BN);
            #pragma unroll
            for (int k = 0; k < KKC; k++) {
                // FIX (R1 bug): use the GLOBAL feature index kk*KKC + k into As,
                // not the chunk-local k. Previous round contracted x[:,0:16]
                // against every W chunk -> rel_err 0.112.
                const float* Arow = &As[(kk * KKC + k) * AS_STRIDE + ty * TM];
                float4 a0 = *reinterpret_cast<const float4*>(Arow);
                float4 a1 = *reinterpret_cast<const float4*>(Arow + 4);
                float a[TM] = {a0.x, a0.y, a0.z, a0.w, a1.x, a1.y, a1.z, a1.w};
                float bf[NC];
                #pragma unroll
                for (int d = 0; d < NC; d++) bf[d] = B0[k * BN + d * NR + tx];
                #pragma unroll
                for (int m = 0; m < TM; m++)
                    #pragma unroll
                    for (int d = 0; d < NC; d++)
                        acc[m][d] = fmaf(a[m], bf[d], acc[m][d]);
            }
            __syncthreads();
        }

        // ---- epilogue for this c: bias + row softmax over d + p-weighting ----
        #pragma unroll
        for (int m = 0; m < TM; m++) {
            float v[NC];
            float mx = -1e30f;
            #pragma unroll
            for (int d = 0; d < NC; d++) {
                v[d] = acc[m][d] + biass[c * BN + d * NR + tx];
                mx = fmaxf(mx, v[d]);
            }
            float s = 0.f;
            #pragma unroll
            for (int d = 0; d < NC; d++) {
                v[d] = __expf(v[d] - mx);
                s += v[d];
            }
            float pv = ps[(ty * TM + m) * NC + c];
            float sc = __fdividef(pv, s);
            #pragma unroll
            for (int d = 0; d < NC; d++) outreg[m][d] += v[d] * sc;
        }
    }

    // ---- write output (B, C, R): fully covers d_out ----
    #pragma unroll
    for (int m = 0; m < TM; m++) {
        size_t row = rowbase + ty * TM + m;
        #pragma unroll
        for (int d = 0; d < NC; d++)
            out[row * BN + d * NR + tx] = outreg[m][d];
    }
}

extern "C" void kernel_launch(void* const* d_in, const int* in_sizes, int n_in,
                              void* d_out, int out_size) {
    const float* x    = (const float*)d_in[0];   // (B, 128)
    const float* p    = (const float*)d_in[1];   // (B, 8)
    const float* W    = (const float*)d_in[2];   // (128, 4096)
    const float* bias = (const float*)d_in[3];   // (4096,)
    float* out = (float*)d_out;

    int B = in_sizes[0] / NF;                    // 16384
    int grid = B / BM;                           // 512

    size_t smem_bytes = (NF * AS_STRIDE + 2 * KKC * BN + NC * BN + BM * NC) * sizeof(float);
    cudaFuncSetAttribute(crowds_fused_kernel,
                         cudaFuncAttributeMaxDynamicSharedMemorySize,
                         (int)smem_bytes);

    crowds_fused_kernel<<<grid, NTHREADS, smem_bytes>>>(x, p, W, bias, out);
}